// round 4
// baseline (speedup 1.0000x reference)
#include <cuda_runtime.h>
#include <cuda_bf16.h>
#include <cstdint>

// Problem constants (capacities; runtime sizes derived from in_sizes)
#define MAXN 50000
#define MAXE 500000
#define HDIM 128

// ---------------- scratch (device globals; no allocations allowed) ----------
__device__ int   g_is64;
__device__ int   g_counts [MAXN];
__device__ int   g_offsets[MAXN + 1];
__device__ int   g_cursor [MAXN];
__device__ int   g_sorted [MAXE];
__device__ float g_agg    [(size_t)MAXN * 4 * HDIM];     // 102.4 MB, [n][c][h] same layout as x
__device__ float g_wcat   [4 * 256 * HDIM];              // [c][k][o]: k<128 -> Wroot[o][k], k>=128 -> Wrel[o][k-128]

// ---------------- kernels ---------------------------------------------------

// Detect whether edge_index arrived as int64 or int32. With int32 data the
// int64 reinterpretation packs two random indices -> huge values -> detected.
__global__ void detect_kernel(const void* __restrict__ ei, int e, int n) {
    const long long* p64 = (const long long*)ei;
    int cnt = e < 256 ? e : 256;
    int ok = 1;
    for (int i = 0; i < cnt; i++) {
        long long v = p64[i];
        if (v < 0 || v >= (long long)n) { ok = 0; break; }
    }
    g_is64 = ok;
}

__global__ void zero_counts_kernel(int n) {
    int i = blockIdx.x * blockDim.x + threadIdx.x;
    if (i < n) g_counts[i] = 0;
}

__global__ void count_kernel(const void* __restrict__ ei, int e) {
    int i = blockIdx.x * blockDim.x + threadIdx.x;
    if (i < e) {
        int r;
        if (g_is64) r = (int)((const long long*)ei)[i];
        else        r = ((const int*)ei)[i];
        atomicAdd(&g_counts[r], 1);
    }
}

// single-block exclusive scan over g_counts -> g_offsets, g_cursor
__global__ void scan_kernel(int n) {
    __shared__ int sh[1024];
    int tid = threadIdx.x;
    int per = (n + 1023) >> 10;
    int base = tid * per;
    int s = 0;
    for (int i = 0; i < per; i++) {
        int idx = base + i;
        if (idx < n) s += g_counts[idx];
    }
    sh[tid] = s;
    __syncthreads();
    for (int off = 1; off < 1024; off <<= 1) {
        int t = (tid >= off) ? sh[tid - off] : 0;
        __syncthreads();
        sh[tid] += t;
        __syncthreads();
    }
    int run = sh[tid] - s;  // exclusive prefix for this thread's chunk
    for (int i = 0; i < per; i++) {
        int idx = base + i;
        if (idx < n) {
            g_offsets[idx] = run;
            g_cursor[idx]  = run;
            run += g_counts[idx];
        }
    }
    if (tid == 1023) g_offsets[n] = sh[1023];
}

__global__ void fill_kernel(const void* __restrict__ ei, int e) {
    int i = blockIdx.x * blockDim.x + threadIdx.x;
    if (i < e) {
        int r, c;
        if (g_is64) {
            const long long* p = (const long long*)ei;
            r = (int)p[i];
            c = (int)p[(size_t)e + i];
        } else {
            const int* p = (const int*)ei;
            r = p[i];
            c = p[(size_t)e + i];
        }
        int pos = atomicAdd(&g_cursor[r], 1);
        g_sorted[pos] = c;
    }
}

// one block (128 threads) per node: agg[n][:] = sum over incoming edges of x[col][:]
__global__ void agg_kernel(const float* __restrict__ x) {
    int nidx = blockIdx.x;
    int tid  = threadIdx.x;           // owns float4 slot tid of 128 (512 floats)
    int beg = g_offsets[nidx];
    int end = g_offsets[nidx + 1];
    const float4* xv = (const float4*)x;
    float4 acc = make_float4(0.f, 0.f, 0.f, 0.f);
    int j = beg;
    for (; j + 1 < end; j += 2) {
        int c0 = g_sorted[j];
        int c1 = g_sorted[j + 1];
        float4 v0 = xv[(size_t)c0 * 128 + tid];
        float4 v1 = xv[(size_t)c1 * 128 + tid];
        acc.x += v0.x; acc.y += v0.y; acc.z += v0.z; acc.w += v0.w;
        acc.x += v1.x; acc.y += v1.y; acc.z += v1.z; acc.w += v1.w;
    }
    if (j < end) {
        int c0 = g_sorted[j];
        float4 v0 = xv[(size_t)c0 * 128 + tid];
        acc.x += v0.x; acc.y += v0.y; acc.z += v0.z; acc.w += v0.w;
    }
    ((float4*)g_agg)[(size_t)nidx * 128 + tid] = acc;
}

// build concatenated, K-major weight buffer: g_wcat[c][k][o]
__global__ void wcat_kernel(const float* __restrict__ Wsrel,
                            const float* __restrict__ Wsroot,
                            const float* __restrict__ Wvrel,
                            const float* __restrict__ Wvroot) {
    int idx = blockIdx.x * blockDim.x + threadIdx.x;
    const int total = 4 * 256 * 128;
    if (idx >= total) return;
    int o = idx & 127;
    int k = (idx >> 7) & 255;
    int c = idx >> 15;
    const float* root = (c == 0) ? Wsroot : Wvroot;
    const float* rel  = (c == 0) ? Wsrel  : Wvrel;
    float v = (k < 128) ? root[o * 128 + k] : rel[o * 128 + (k - 128)];
    g_wcat[idx] = v;
}

// out[n,c,:] = [x(n,c,:) | agg(n,c,:)] @ Wcat_c + (c==0 ? bias : 0)
// tile: BM=64 rows, BN=128 cols, BK=16; 256 threads, 4x(4+4) microtile
__global__ __launch_bounds__(256) void gemm_kernel(const float* __restrict__ x,
                                                   const float* __restrict__ bias,
                                                   float* __restrict__ out,
                                                   int n) {
    __shared__ float As[16][68];    // [k][row], padded (68 % 4 == 0 for float4 reads)
    __shared__ float Bs[16][128];   // [k][o]

    int c    = blockIdx.y;
    int row0 = blockIdx.x * 64;
    int tid  = threadIdx.x;
    int tx   = tid & 15;            // 0..15 -> cols tx*4 and 64+tx*4
    int ty   = tid >> 4;            // 0..15 -> rows ty*4..ty*4+3

    float acc0[4][4];
    float acc1[4][4];
#pragma unroll
    for (int i = 0; i < 4; i++)
#pragma unroll
        for (int j = 0; j < 4; j++) { acc0[i][j] = 0.f; acc1[i][j] = 0.f; }

    const float* B = g_wcat + (size_t)c * 256 * 128;

    int arow = tid >> 2;            // 0..63
    int ak   = (tid & 3) * 4;       // 0,4,8,12
    int brow = tid >> 4;            // 0..15
    int bcol = (tid & 15) * 8;      // 0..120

    for (int k0 = 0; k0 < 256; k0 += 16) {
        // ---- load A tile (64 rows x 16 k) ----
        int gk = k0 + ak;
        const float* src = (gk < 128) ? x : (const float*)g_agg;
        int koff = gk & 127;
        int nn = row0 + arow;
        float4 av = make_float4(0.f, 0.f, 0.f, 0.f);
        if (nn < n) {
            av = *(const float4*)&src[((size_t)nn * 4 + c) * 128 + koff];
        }
        As[ak + 0][arow] = av.x;
        As[ak + 1][arow] = av.y;
        As[ak + 2][arow] = av.z;
        As[ak + 3][arow] = av.w;

        // ---- load B tile (16 k x 128 o) ----
        const float* bp = B + (size_t)(k0 + brow) * 128 + bcol;
        float4 b0 = *(const float4*)bp;
        float4 b1 = *(const float4*)(bp + 4);
        *(float4*)&Bs[brow][bcol]     = b0;
        *(float4*)&Bs[brow][bcol + 4] = b1;

        __syncthreads();

#pragma unroll
        for (int kk = 0; kk < 16; kk++) {
            float4 a   = *(const float4*)&As[kk][ty * 4];
            float4 bv0 = *(const float4*)&Bs[kk][tx * 4];
            float4 bv1 = *(const float4*)&Bs[kk][64 + tx * 4];
            float ar[4] = {a.x, a.y, a.z, a.w};
            float b0r[4] = {bv0.x, bv0.y, bv0.z, bv0.w};
            float b1r[4] = {bv1.x, bv1.y, bv1.z, bv1.w};
#pragma unroll
            for (int i = 0; i < 4; i++) {
#pragma unroll
                for (int j = 0; j < 4; j++) {
                    acc0[i][j] += ar[i] * b0r[j];
                    acc1[i][j] += ar[i] * b1r[j];
                }
            }
        }
        __syncthreads();
    }

    // ---- epilogue ----
    float4 bi0 = make_float4(0.f, 0.f, 0.f, 0.f);
    float4 bi1 = make_float4(0.f, 0.f, 0.f, 0.f);
    if (c == 0) {
        bi0 = *(const float4*)&bias[tx * 4];
        bi1 = *(const float4*)&bias[64 + tx * 4];
    }
#pragma unroll
    for (int i = 0; i < 4; i++) {
        int nn = row0 + ty * 4 + i;
        if (nn < n) {
            float* op = out + ((size_t)nn * 4 + c) * 128;
            float4 r0 = make_float4(acc0[i][0] + bi0.x, acc0[i][1] + bi0.y,
                                    acc0[i][2] + bi0.z, acc0[i][3] + bi0.w);
            float4 r1 = make_float4(acc1[i][0] + bi1.x, acc1[i][1] + bi1.y,
                                    acc1[i][2] + bi1.z, acc1[i][3] + bi1.w);
            *(float4*)&op[tx * 4]      = r0;
            *(float4*)&op[64 + tx * 4] = r1;
        }
    }
}

// ---------------- launch -----------------------------------------------------

extern "C" void kernel_launch(void* const* d_in, const int* in_sizes, int n_in,
                              void* d_out, int out_size) {
    const float* x      = (const float*)d_in[0];
    const void*  ei     = d_in[1];
    const float* Wsrel  = (const float*)d_in[2];
    const float* Wsroot = (const float*)d_in[3];
    const float* bs     = (const float*)d_in[4];
    const float* Wvrel  = (const float*)d_in[5];
    const float* Wvroot = (const float*)d_in[6];
    float*       out    = (float*)d_out;

    int n = in_sizes[0] / (4 * HDIM);   // 50000
    int e = in_sizes[1] / 2;            // 500000

    // dtype detection for edge_index (int32 vs int64)
    detect_kernel<<<1, 1>>>(ei, e, n);

    // CSR build
    zero_counts_kernel<<<(n + 255) / 256, 256>>>(n);
    count_kernel<<<(e + 255) / 256, 256>>>(ei, e);
    scan_kernel<<<1, 1024>>>(n);
    fill_kernel<<<(e + 255) / 256, 256>>>(ei, e);

    // weight prep (independent; cheap)
    wcat_kernel<<<(4 * 256 * 128 + 255) / 256, 256>>>(Wsrel, Wsroot, Wvrel, Wvroot);

    // aggregate neighbor features
    agg_kernel<<<n, 128>>>(x);

    // fused dual-GEMM + bias
    dim3 grid((n + 63) / 64, 4);
    gemm_kernel<<<grid, 256>>>(x, bs, out, n);
}

// round 5
// speedup vs baseline: 1.0587x; 1.0587x over previous
#include <cuda_runtime.h>
#include <cuda_bf16.h>
#include <cstdint>

// Problem constants (capacities; runtime sizes derived from in_sizes)
#define MAXN 50000
#define MAXE 500000
#define HDIM 128

// ---------------- scratch (device globals; no allocations allowed) ----------
__device__ int   g_is64;
__device__ int   g_counts [MAXN];
__device__ int   g_offsets[MAXN + 1];
__device__ int   g_cursor [MAXN];
__device__ int   g_sorted [MAXE];
__device__ int   g_bsum   [256];
__device__ int   g_boff   [256];
__device__ int   g_total;
__device__ float g_agg    [(size_t)MAXN * 4 * HDIM];     // 102.4 MB, [n][c][h] same layout as x
__device__ float g_wcat   [4 * 256 * HDIM];              // [c][k][o]

// packed fp32x2 FMA (sm_103a): d = a*b + c on both 32-bit lanes
#define FMA2(d, a, b, c) \
    asm("fma.rn.f32x2 %0, %1, %2, %3;" : "=l"(d) : "l"(a), "l"(b), "l"(c))

__device__ __forceinline__ float2 u2f(unsigned long long v) {
    float2 r;
    asm("mov.b64 {%0, %1}, %2;" : "=f"(r.x), "=f"(r.y) : "l"(v));
    return r;
}

// ---------------- kernels ---------------------------------------------------

// Detect whether edge_index arrived as int64 or int32.
__global__ void detect_kernel(const void* __restrict__ ei, int e, int n) {
    const long long* p64 = (const long long*)ei;
    int cnt = e < 256 ? e : 256;
    int ok = 1;
    for (int i = 0; i < cnt; i++) {
        long long v = p64[i];
        if (v < 0 || v >= (long long)n) { ok = 0; break; }
    }
    g_is64 = ok;
}

__global__ void zero_counts_kernel(int n) {
    int i = blockIdx.x * blockDim.x + threadIdx.x;
    if (i < n) g_counts[i] = 0;
}

__global__ void count_kernel(const void* __restrict__ ei, int e) {
    int i = blockIdx.x * blockDim.x + threadIdx.x;
    if (i < e) {
        int r;
        if (g_is64) r = (int)((const long long*)ei)[i];
        else        r = ((const int*)ei)[i];
        atomicAdd(&g_counts[r], 1);
    }
}

// ---- 3-phase multi-block exclusive scan of g_counts -> g_offsets/g_cursor ---

// phase 1: per-block (256 elems) exclusive scan into g_offsets (block-local),
// block total into g_bsum
__global__ void scan1_kernel(int n) {
    int tid  = threadIdx.x;
    int gid  = blockIdx.x * 256 + tid;
    int lane = tid & 31;
    int wid  = tid >> 5;
    int v = (gid < n) ? g_counts[gid] : 0;
    int s = v;
#pragma unroll
    for (int o = 1; o < 32; o <<= 1) {
        int t = __shfl_up_sync(0xFFFFFFFFu, s, o);
        if (lane >= o) s += t;
    }
    __shared__ int wtot[8];
    __shared__ int woff[8];
    if (lane == 31) wtot[wid] = s;
    __syncthreads();
    if (tid == 0) {
        int r = 0;
#pragma unroll
        for (int w = 0; w < 8; w++) { woff[w] = r; r += wtot[w]; }
        g_bsum[blockIdx.x] = r;
    }
    __syncthreads();
    int excl = s - v + woff[wid];
    if (gid < n) g_offsets[gid] = excl;
}

// phase 2: single block scans the (<=256) block sums
__global__ void scan2_kernel(int nb) {
    int tid  = threadIdx.x;
    int lane = tid & 31;
    int wid  = tid >> 5;
    int v = (tid < nb) ? g_bsum[tid] : 0;
    int s = v;
#pragma unroll
    for (int o = 1; o < 32; o <<= 1) {
        int t = __shfl_up_sync(0xFFFFFFFFu, s, o);
        if (lane >= o) s += t;
    }
    __shared__ int wtot[8];
    __shared__ int woff[8];
    if (lane == 31) wtot[wid] = s;
    __syncthreads();
    if (tid == 0) {
        int r = 0;
#pragma unroll
        for (int w = 0; w < 8; w++) { woff[w] = r; r += wtot[w]; }
        g_total = r;
    }
    __syncthreads();
    g_boff[tid] = s - v + woff[wid];
}

// phase 3: add block offsets, init cursor, write sentinel
__global__ void scan3_kernel(int n) {
    int gid = blockIdx.x * 256 + threadIdx.x;
    if (gid < n) {
        int off = g_offsets[gid] + g_boff[gid >> 8];
        g_offsets[gid] = off;
        g_cursor[gid]  = off;
    }
    if (gid == 0) g_offsets[n] = g_total;
}

__global__ void fill_kernel(const void* __restrict__ ei, int e) {
    int i = blockIdx.x * blockDim.x + threadIdx.x;
    if (i < e) {
        int r, c;
        if (g_is64) {
            const long long* p = (const long long*)ei;
            r = (int)p[i];
            c = (int)p[(size_t)e + i];
        } else {
            const int* p = (const int*)ei;
            r = p[i];
            c = p[(size_t)e + i];
        }
        int pos = atomicAdd(&g_cursor[r], 1);
        g_sorted[pos] = c;
    }
}

// one block (128 threads) per node: agg[n][:] = sum over incoming edges of x[col][:]
__global__ void agg_kernel(const float* __restrict__ x) {
    int nidx = blockIdx.x;
    int tid  = threadIdx.x;
    int beg = g_offsets[nidx];
    int end = g_offsets[nidx + 1];
    const float4* xv = (const float4*)x;
    float4 acc = make_float4(0.f, 0.f, 0.f, 0.f);
    int j = beg;
    for (; j + 1 < end; j += 2) {
        int c0 = g_sorted[j];
        int c1 = g_sorted[j + 1];
        float4 v0 = xv[(size_t)c0 * 128 + tid];
        float4 v1 = xv[(size_t)c1 * 128 + tid];
        acc.x += v0.x; acc.y += v0.y; acc.z += v0.z; acc.w += v0.w;
        acc.x += v1.x; acc.y += v1.y; acc.z += v1.z; acc.w += v1.w;
    }
    if (j < end) {
        int c0 = g_sorted[j];
        float4 v0 = xv[(size_t)c0 * 128 + tid];
        acc.x += v0.x; acc.y += v0.y; acc.z += v0.z; acc.w += v0.w;
    }
    ((float4*)g_agg)[(size_t)nidx * 128 + tid] = acc;
}

// build concatenated, K-major weight buffer: g_wcat[c][k][o]
__global__ void wcat_kernel(const float* __restrict__ Wsrel,
                            const float* __restrict__ Wsroot,
                            const float* __restrict__ Wvrel,
                            const float* __restrict__ Wvroot) {
    int idx = blockIdx.x * blockDim.x + threadIdx.x;
    const int total = 4 * 256 * 128;
    if (idx >= total) return;
    int o = idx & 127;
    int k = (idx >> 7) & 255;
    int c = idx >> 15;
    const float* root = (c == 0) ? Wsroot : Wvroot;
    const float* rel  = (c == 0) ? Wsrel  : Wvrel;
    float v = (k < 128) ? root[o * 128 + k] : rel[o * 128 + (k - 128)];
    g_wcat[idx] = v;
}

// out[n,c,:] = [x(n,c,:) | agg(n,c,:)] @ Wcat_c + (c==0 ? bias : 0)
// BM=64, BN=128, BK=16; 256 threads; 4x8 microtile via packed fma.rn.f32x2.
// A tile is stored DUPLICATED ((a,a) per float2) so the broadcast operand of
// the packed FMA loads directly from SMEM with no pack instructions.
__global__ __launch_bounds__(256) void gemm_kernel(const float* __restrict__ x,
                                                   const float* __restrict__ bias,
                                                   float* __restrict__ out,
                                                   int n) {
    __shared__ float2 As2[16][66];   // [k][row], duplicated values, padded
    __shared__ float  Bs[16][128];   // [k][o]

    int c    = blockIdx.y;
    int row0 = blockIdx.x * 64;
    int tid  = threadIdx.x;
    int tx   = tid & 15;            // cols tx*4..+3 and 64+tx*4..+3
    int ty   = tid >> 4;            // rows ty*4..+3

    // acc[i][p]: row i, pair p (p=0,1 -> cols tx*4+2p..; p=2,3 -> 64+tx*4+2(p-2)..)
    unsigned long long acc[4][4];
#pragma unroll
    for (int i = 0; i < 4; i++)
#pragma unroll
        for (int p = 0; p < 4; p++) acc[i][p] = 0ULL;

    const float* B = g_wcat + (size_t)c * 256 * 128;

    int arow = tid >> 2;            // 0..63
    int ak   = (tid & 3) * 4;       // 0,4,8,12
    int brow = tid >> 4;            // 0..15
    int bcol = (tid & 15) * 8;      // 0..120

    for (int k0 = 0; k0 < 256; k0 += 16) {
        // ---- load A tile (64 rows x 16 k), store duplicated ----
        int gk = k0 + ak;
        const float* src = (gk < 128) ? x : (const float*)g_agg;
        int koff = gk & 127;
        int nn = row0 + arow;
        float4 av = make_float4(0.f, 0.f, 0.f, 0.f);
        if (nn < n) {
            av = *(const float4*)&src[((size_t)nn * 4 + c) * 128 + koff];
        }
        As2[ak + 0][arow] = make_float2(av.x, av.x);
        As2[ak + 1][arow] = make_float2(av.y, av.y);
        As2[ak + 2][arow] = make_float2(av.z, av.z);
        As2[ak + 3][arow] = make_float2(av.w, av.w);

        // ---- load B tile (16 k x 128 o) ----
        const float* bp = B + (size_t)(k0 + brow) * 128 + bcol;
        float4 b0 = *(const float4*)bp;
        float4 b1 = *(const float4*)(bp + 4);
        *(float4*)&Bs[brow][bcol]     = b0;
        *(float4*)&Bs[brow][bcol + 4] = b1;

        __syncthreads();

#pragma unroll
        for (int kk = 0; kk < 16; kk++) {
            ulonglong2 a01 = *(const ulonglong2*)&As2[kk][ty * 4];
            ulonglong2 a23 = *(const ulonglong2*)&As2[kk][ty * 4 + 2];
            ulonglong2 bl0 = *(const ulonglong2*)&Bs[kk][tx * 4];
            ulonglong2 bl1 = *(const ulonglong2*)&Bs[kk][64 + tx * 4];
            unsigned long long ar[4] = {a01.x, a01.y, a23.x, a23.y};
            unsigned long long br[4] = {bl0.x, bl0.y, bl1.x, bl1.y};
#pragma unroll
            for (int i = 0; i < 4; i++) {
#pragma unroll
                for (int p = 0; p < 4; p++) {
                    FMA2(acc[i][p], ar[i], br[p], acc[i][p]);
                }
            }
        }
        __syncthreads();
    }

    // ---- epilogue ----
    float4 bi0 = make_float4(0.f, 0.f, 0.f, 0.f);
    float4 bi1 = make_float4(0.f, 0.f, 0.f, 0.f);
    if (c == 0) {
        bi0 = *(const float4*)&bias[tx * 4];
        bi1 = *(const float4*)&bias[64 + tx * 4];
    }
#pragma unroll
    for (int i = 0; i < 4; i++) {
        int nn = row0 + ty * 4 + i;
        if (nn < n) {
            float* op = out + ((size_t)nn * 4 + c) * 128;
            float2 p0 = u2f(acc[i][0]);
            float2 p1 = u2f(acc[i][1]);
            float2 p2 = u2f(acc[i][2]);
            float2 p3 = u2f(acc[i][3]);
            float4 r0 = make_float4(p0.x + bi0.x, p0.y + bi0.y,
                                    p1.x + bi0.z, p1.y + bi0.w);
            float4 r1 = make_float4(p2.x + bi1.x, p2.y + bi1.y,
                                    p3.x + bi1.z, p3.y + bi1.w);
            *(float4*)&op[tx * 4]      = r0;
            *(float4*)&op[64 + tx * 4] = r1;
        }
    }
}

// ---------------- launch -----------------------------------------------------

extern "C" void kernel_launch(void* const* d_in, const int* in_sizes, int n_in,
                              void* d_out, int out_size) {
    const float* x      = (const float*)d_in[0];
    const void*  ei     = d_in[1];
    const float* Wsrel  = (const float*)d_in[2];
    const float* Wsroot = (const float*)d_in[3];
    const float* bs     = (const float*)d_in[4];
    const float* Wvrel  = (const float*)d_in[5];
    const float* Wvroot = (const float*)d_in[6];
    float*       out    = (float*)d_out;

    int n = in_sizes[0] / (4 * HDIM);   // 50000
    int e = in_sizes[1] / 2;            // 500000
    int nb = (n + 255) / 256;           // scan blocks (<=256)

    // dtype detection for edge_index (int32 vs int64)
    detect_kernel<<<1, 1>>>(ei, e, n);

    // CSR build
    zero_counts_kernel<<<(n + 255) / 256, 256>>>(n);
    count_kernel<<<(e + 255) / 256, 256>>>(ei, e);
    scan1_kernel<<<nb, 256>>>(n);
    scan2_kernel<<<1, 256>>>(nb);
    scan3_kernel<<<nb, 256>>>(n);
    fill_kernel<<<(e + 255) / 256, 256>>>(ei, e);

    // weight prep (independent; cheap)
    wcat_kernel<<<(4 * 256 * 128 + 255) / 256, 256>>>(Wsrel, Wsroot, Wvrel, Wvroot);

    // aggregate neighbor features
    agg_kernel<<<n, 128>>>(x);

    // fused dual-GEMM + bias (packed f32x2 FMA)
    dim3 grid((n + 63) / 64, 4);
    gemm_kernel<<<grid, 256>>>(x, bs, out, n);
}

// round 12
// speedup vs baseline: 1.6736x; 1.5808x over previous
#include <cuda_runtime.h>
#include <cuda_bf16.h>
#include <cstdint>

// Problem constants
#define MAXN 50000
#define MAXE 500000
#define HDIM 128

// ---------------- scratch (device globals) -----------------------------------
__device__ int   g_is64;
__device__ int   g_counts [MAXN];
__device__ int   g_offsets[MAXN + 1];
__device__ int   g_cursor [MAXN];
__device__ int   g_sorted [MAXE];
__device__ int   g_bsum   [256];
__device__ int   g_boff   [256];
__device__ int   g_total;
__device__ float g_agg    [(size_t)MAXN * 4 * HDIM];          // [n][c][h], 102.4 MB
// bf16 split weights, [c][o][k256]: k<128 -> Wroot[o][k], else Wrel[o][k-128]
__device__ __nv_bfloat16 g_whi[4 * 128 * 256];
__device__ __nv_bfloat16 g_wlo[4 * 128 * 256];

// ---------------- helpers ------------------------------------------------------
__device__ __forceinline__ uint32_t smem_u32(const void* p) {
    uint32_t a;
    asm("{ .reg .u64 t; cvta.to.shared.u64 t, %1; cvt.u32.u64 %0, t; }"
        : "=r"(a) : "l"(p));
    return a;
}

__device__ __forceinline__ void ldsm_x4(uint32_t* r, uint32_t addr) {
    asm volatile("ldmatrix.sync.aligned.m8n8.x4.shared.b16 {%0,%1,%2,%3}, [%4];"
                 : "=r"(r[0]), "=r"(r[1]), "=r"(r[2]), "=r"(r[3]) : "r"(addr));
}
__device__ __forceinline__ void mma_bf16(float* d, const uint32_t* a,
                                         uint32_t b0, uint32_t b1) {
    asm volatile(
        "mma.sync.aligned.m16n8k16.row.col.f32.bf16.bf16.f32 "
        "{%0,%1,%2,%3}, {%4,%5,%6,%7}, {%8,%9}, {%0,%1,%2,%3};"
        : "+f"(d[0]), "+f"(d[1]), "+f"(d[2]), "+f"(d[3])
        : "r"(a[0]), "r"(a[1]), "r"(a[2]), "r"(a[3]), "r"(b0), "r"(b1));
}

// ---------------- CSR / agg kernels -------------------------------------------
__global__ void detect_kernel(const void* __restrict__ ei, int e, int n) {
    const long long* p64 = (const long long*)ei;
    int cnt = e < 256 ? e : 256;
    int ok = 1;
    for (int i = 0; i < cnt; i++) {
        long long v = p64[i];
        if (v < 0 || v >= (long long)n) { ok = 0; break; }
    }
    g_is64 = ok;
}

__global__ void zero_counts_kernel(int n) {
    int i = blockIdx.x * blockDim.x + threadIdx.x;
    if (i < n) g_counts[i] = 0;
}

__global__ void count_kernel(const void* __restrict__ ei, int e) {
    int i = blockIdx.x * blockDim.x + threadIdx.x;
    if (i < e) {
        int r;
        if (g_is64) r = (int)((const long long*)ei)[i];
        else        r = ((const int*)ei)[i];
        atomicAdd(&g_counts[r], 1);
    }
}

__global__ void scan1_kernel(int n) {
    int tid  = threadIdx.x;
    int gid  = blockIdx.x * 256 + tid;
    int lane = tid & 31;
    int wid  = tid >> 5;
    int v = (gid < n) ? g_counts[gid] : 0;
    int s = v;
#pragma unroll
    for (int o = 1; o < 32; o <<= 1) {
        int t = __shfl_up_sync(0xFFFFFFFFu, s, o);
        if (lane >= o) s += t;
    }
    __shared__ int wtot[8];
    __shared__ int woff[8];
    if (lane == 31) wtot[wid] = s;
    __syncthreads();
    if (tid == 0) {
        int r = 0;
#pragma unroll
        for (int w = 0; w < 8; w++) { woff[w] = r; r += wtot[w]; }
        g_bsum[blockIdx.x] = r;
    }
    __syncthreads();
    int excl = s - v + woff[wid];
    if (gid < n) g_offsets[gid] = excl;
}

__global__ void scan2_kernel(int nb) {
    int tid  = threadIdx.x;
    int lane = tid & 31;
    int wid  = tid >> 5;
    int v = (tid < nb) ? g_bsum[tid] : 0;
    int s = v;
#pragma unroll
    for (int o = 1; o < 32; o <<= 1) {
        int t = __shfl_up_sync(0xFFFFFFFFu, s, o);
        if (lane >= o) s += t;
    }
    __shared__ int wtot[8];
    __shared__ int woff[8];
    if (lane == 31) wtot[wid] = s;
    __syncthreads();
    if (tid == 0) {
        int r = 0;
#pragma unroll
        for (int w = 0; w < 8; w++) { woff[w] = r; r += wtot[w]; }
        g_total = r;
    }
    __syncthreads();
    g_boff[tid] = s - v + woff[wid];
}

__global__ void scan3_kernel(int n) {
    int gid = blockIdx.x * 256 + threadIdx.x;
    if (gid < n) {
        int off = g_offsets[gid] + g_boff[gid >> 8];
        g_offsets[gid] = off;
        g_cursor[gid]  = off;
    }
    if (gid == 0) g_offsets[n] = g_total;
}

__global__ void fill_kernel(const void* __restrict__ ei, int e) {
    int i = blockIdx.x * blockDim.x + threadIdx.x;
    if (i < e) {
        int r, c;
        if (g_is64) {
            const long long* p = (const long long*)ei;
            r = (int)p[i];
            c = (int)p[(size_t)e + i];
        } else {
            const int* p = (const int*)ei;
            r = p[i];
            c = p[(size_t)e + i];
        }
        int pos = atomicAdd(&g_cursor[r], 1);
        g_sorted[pos] = c;
    }
}

__global__ void agg_kernel(const float* __restrict__ x) {
    int nidx = blockIdx.x;
    int tid  = threadIdx.x;
    int beg = g_offsets[nidx];
    int end = g_offsets[nidx + 1];
    const float4* xv = (const float4*)x;
    float4 acc = make_float4(0.f, 0.f, 0.f, 0.f);
    int j = beg;
    for (; j + 1 < end; j += 2) {
        int c0 = g_sorted[j];
        int c1 = g_sorted[j + 1];
        float4 v0 = xv[(size_t)c0 * 128 + tid];
        float4 v1 = xv[(size_t)c1 * 128 + tid];
        acc.x += v0.x; acc.y += v0.y; acc.z += v0.z; acc.w += v0.w;
        acc.x += v1.x; acc.y += v1.y; acc.z += v1.z; acc.w += v1.w;
    }
    if (j < end) {
        int c0 = g_sorted[j];
        float4 v0 = xv[(size_t)c0 * 128 + tid];
        acc.x += v0.x; acc.y += v0.y; acc.z += v0.z; acc.w += v0.w;
    }
    ((float4*)g_agg)[(size_t)nidx * 128 + tid] = acc;
}

// weight prep: bf16 hi/lo split, [c][o][k256]
__global__ void wprep_kernel(const float* __restrict__ Wsrel,
                             const float* __restrict__ Wsroot,
                             const float* __restrict__ Wvrel,
                             const float* __restrict__ Wvroot) {
    int idx = blockIdx.x * blockDim.x + threadIdx.x;
    const int total = 4 * 128 * 256;
    if (idx >= total) return;
    int k = idx & 255;
    int o = (idx >> 8) & 127;
    int c = idx >> 15;
    const float* root = (c == 0) ? Wsroot : Wvroot;
    const float* rel  = (c == 0) ? Wsrel  : Wvrel;
    float w = (k < 128) ? root[o * 128 + k] : rel[o * 128 + (k - 128)];
    __nv_bfloat16 hi = __float2bfloat16(w);
    __nv_bfloat16 lo = __float2bfloat16(w - __bfloat162float(hi));
    g_whi[idx] = hi;
    g_wlo[idx] = lo;
}

// ---------------- HMMA GEMM ----------------------------------------------------
// grid (ceil(n/128), 4), 256 threads (8 warps 4x2), dyn smem 64KB.
// out[n,c,:] = [x | agg](n,c,:) @ Wcat_c^T (+bias if c==0), bf16 split 3-product.
// SMEM tiles: A 128(m)x64(k) bf16 hi/lo; B 128(n)x64(k) bf16 hi/lo.
// Both A and B are k-contiguous per row -> both use NON-trans ldmatrix
// (B stored [n][k] == col-major KxN, the exact b-fragment layout of
// mma.m16n8k16.row.col).
// Row = 128B; 16B chunks XOR-swizzled: off = r*128 + ((kc ^ (r&7))<<4).

#define SM_AHI 0
#define SM_ALO 16384
#define SM_BHI 32768
#define SM_BLO 49152
#define SM_TOT 65536

__global__ __launch_bounds__(256) void hmma_gemm_kernel(const float* __restrict__ x,
                                                        const float* __restrict__ bias,
                                                        float* __restrict__ out,
                                                        int n) {
    extern __shared__ char smem[];
    uint32_t sb = smem_u32(smem);

    int tid  = threadIdx.x;
    int lane = tid & 31;
    int warp = tid >> 5;
    int wm   = warp & 3;     // 0..3  -> 32 M rows each
    int wn   = warp >> 2;    // 0..1  -> 64 N cols each
    int c    = blockIdx.y;
    int row0 = blockIdx.x * 128;

    int q   = lane >> 3;     // ldmatrix lane group
    int rib = lane & 7;
    int qm  = (q & 1) * 8;
    int qk  = q >> 1;

    // fixed ldmatrix row indices
    int rA0 = wm * 32 + qm + rib;
    int rA1 = rA0 + 16;
    int rB[4];
#pragma unroll
    for (int p = 0; p < 4; p++) rB[p] = wn * 64 + p * 16 + qm + rib;

    float acc[2][8][4];
#pragma unroll
    for (int mt = 0; mt < 2; mt++)
#pragma unroll
        for (int nt = 0; nt < 8; nt++)
#pragma unroll
            for (int i = 0; i < 4; i++) acc[mt][nt][i] = 0.f;

    const uint32_t aBase[3] = {SM_AHI, SM_AHI, SM_ALO};
    const uint32_t bBase[3] = {SM_BHI, SM_BLO, SM_BHI};

    for (int k0c = 0; k0c < 4; k0c++) {
        if (k0c) __syncthreads();   // protect smem reuse

        // ---- A chunk: 128 rows x 64 k fp32 -> bf16 hi/lo swizzled ----
        const float* asrc = (k0c < 2) ? x : (const float*)g_agg;
        int kbase = (k0c & 1) * 64;
#pragma unroll
        for (int it = 0; it < 8; it++) {
            int idx = it * 256 + tid;
            int r   = idx >> 4;           // 0..127
            int f4  = idx & 15;           // float4 within row
            float4 v = make_float4(0.f, 0.f, 0.f, 0.f);
            int nn = row0 + r;
            if (nn < n)
                v = *(const float4*)&asrc[((size_t)nn * 4 + c) * 128 + kbase + f4 * 4];
            __nv_bfloat16 h0 = __float2bfloat16(v.x);
            __nv_bfloat16 h1 = __float2bfloat16(v.y);
            __nv_bfloat16 h2 = __float2bfloat16(v.z);
            __nv_bfloat16 h3 = __float2bfloat16(v.w);
            __nv_bfloat16 l0 = __float2bfloat16(v.x - __bfloat162float(h0));
            __nv_bfloat16 l1 = __float2bfloat16(v.y - __bfloat162float(h1));
            __nv_bfloat16 l2 = __float2bfloat16(v.z - __bfloat162float(h2));
            __nv_bfloat16 l3 = __float2bfloat16(v.w - __bfloat162float(h3));
            uint2 hv, lv;
            hv.x = (uint32_t)__bfloat16_as_ushort(h0) | ((uint32_t)__bfloat16_as_ushort(h1) << 16);
            hv.y = (uint32_t)__bfloat16_as_ushort(h2) | ((uint32_t)__bfloat16_as_ushort(h3) << 16);
            lv.x = (uint32_t)__bfloat16_as_ushort(l0) | ((uint32_t)__bfloat16_as_ushort(l1) << 16);
            lv.y = (uint32_t)__bfloat16_as_ushort(l2) | ((uint32_t)__bfloat16_as_ushort(l3) << 16);
            int kc   = f4 >> 1;
            int sub8 = (f4 & 1) << 3;
            uint32_t off = (uint32_t)(r * 128 + ((kc ^ (r & 7)) << 4) + sub8);
            *(uint2*)(smem + SM_AHI + off) = hv;
            *(uint2*)(smem + SM_ALO + off) = lv;
        }

        // ---- B chunk: 128 n x 64 k bf16 hi/lo swizzled ----
        const __nv_bfloat16* wh = g_whi + (size_t)c * 128 * 256 + k0c * 64;
        const __nv_bfloat16* wl = g_wlo + (size_t)c * 128 * 256 + k0c * 64;
#pragma unroll
        for (int it = 0; it < 4; it++) {
            int id = it * 256 + tid;
            int nr = id >> 3;             // 0..127
            int kc = id & 7;              // 16B chunk
            uint4 hv = *(const uint4*)&wh[(size_t)nr * 256 + kc * 8];
            uint4 lv = *(const uint4*)&wl[(size_t)nr * 256 + kc * 8];
            uint32_t off = (uint32_t)(nr * 128 + ((kc ^ (nr & 7)) << 4));
            *(uint4*)(smem + SM_BHI + off) = hv;
            *(uint4*)(smem + SM_BLO + off) = lv;
        }

        __syncthreads();

        // ---- compute: 3 products x 4 k-steps x (2m x 8n) mma ----
#pragma unroll
        for (int p = 0; p < 3; p++) {
            uint32_t ab = sb + aBase[p];
            uint32_t bb = sb + bBase[p];
#pragma unroll
            for (int ks = 0; ks < 4; ks++) {
                int kc = ks * 2 + qk;
                uint32_t a0[4], a1[4];
                ldsm_x4(a0, ab + (uint32_t)(rA0 * 128 + ((kc ^ (rA0 & 7)) << 4)));
                ldsm_x4(a1, ab + (uint32_t)(rA1 * 128 + ((kc ^ (rA1 & 7)) << 4)));
                uint32_t b[4][4];
#pragma unroll
                for (int pr = 0; pr < 4; pr++)
                    ldsm_x4(b[pr], bb + (uint32_t)(rB[pr] * 128 + ((kc ^ (rB[pr] & 7)) << 4)));
#pragma unroll
                for (int pr = 0; pr < 4; pr++) {
                    mma_bf16(acc[0][pr * 2],     a0, b[pr][0], b[pr][2]);
                    mma_bf16(acc[0][pr * 2 + 1], a0, b[pr][1], b[pr][3]);
                    mma_bf16(acc[1][pr * 2],     a1, b[pr][0], b[pr][2]);
                    mma_bf16(acc[1][pr * 2 + 1], a1, b[pr][1], b[pr][3]);
                }
            }
        }
    }

    // ---- epilogue ----
    float2 bv[8];
#pragma unroll
    for (int nt = 0; nt < 8; nt++) bv[nt] = make_float2(0.f, 0.f);
    if (c == 0) {
#pragma unroll
        for (int nt = 0; nt < 8; nt++) {
            int nn = wn * 64 + nt * 8 + (lane & 3) * 2;
            bv[nt] = *(const float2*)&bias[nn];
        }
    }
#pragma unroll
    for (int mt = 0; mt < 2; mt++) {
        int r0 = row0 + wm * 32 + mt * 16 + (lane >> 2);
        int r1 = r0 + 8;
#pragma unroll
        for (int nt = 0; nt < 8; nt++) {
            int nn = wn * 64 + nt * 8 + (lane & 3) * 2;
            if (r0 < n) {
                float2 v = make_float2(acc[mt][nt][0] + bv[nt].x,
                                       acc[mt][nt][1] + bv[nt].y);
                *(float2*)&out[((size_t)r0 * 4 + c) * 128 + nn] = v;
            }
            if (r1 < n) {
                float2 v = make_float2(acc[mt][nt][2] + bv[nt].x,
                                       acc[mt][nt][3] + bv[nt].y);
                *(float2*)&out[((size_t)r1 * 4 + c) * 128 + nn] = v;
            }
        }
    }
}

// ---------------- launch -----------------------------------------------------

extern "C" void kernel_launch(void* const* d_in, const int* in_sizes, int n_in,
                              void* d_out, int out_size) {
    const float* x      = (const float*)d_in[0];
    const void*  ei     = d_in[1];
    const float* Wsrel  = (const float*)d_in[2];
    const float* Wsroot = (const float*)d_in[3];
    const float* bs     = (const float*)d_in[4];
    const float* Wvrel  = (const float*)d_in[5];
    const float* Wvroot = (const float*)d_in[6];
    float*       out    = (float*)d_out;

    int n = in_sizes[0] / (4 * HDIM);   // 50000
    int e = in_sizes[1] / 2;            // 500000
    int nb = (n + 255) / 256;

    cudaFuncSetAttribute(hmma_gemm_kernel,
                         cudaFuncAttributeMaxDynamicSharedMemorySize, SM_TOT);

    detect_kernel<<<1, 1>>>(ei, e, n);

    zero_counts_kernel<<<(n + 255) / 256, 256>>>(n);
    count_kernel<<<(e + 255) / 256, 256>>>(ei, e);
    scan1_kernel<<<nb, 256>>>(n);
    scan2_kernel<<<1, 256>>>(nb);
    scan3_kernel<<<nb, 256>>>(n);
    fill_kernel<<<(e + 255) / 256, 256>>>(ei, e);

    wprep_kernel<<<(4 * 128 * 256 + 255) / 256, 256>>>(Wsrel, Wsroot, Wvrel, Wvroot);

    agg_kernel<<<n, 128>>>(x);

    dim3 grid((n + 127) / 128, 4);
    hmma_gemm_kernel<<<grid, 256, SM_TOT>>>(x, bs, out, n);
}

// round 13
// speedup vs baseline: 2.0215x; 1.2079x over previous
#include <cuda_runtime.h>
#include <cuda_bf16.h>
#include <cstdint>

// Problem constants
#define MAXN 50000
#define MAXE 500000
#define HDIM 128

// ---------------- scratch (device globals) -----------------------------------
__device__ int   g_is64;
__device__ int   g_counts [MAXN];
__device__ int   g_offsets[MAXN + 1];
__device__ int   g_cursor [MAXN];
__device__ int   g_sorted [MAXE];
__device__ int   g_bsum   [256];
__device__ int   g_boff   [256];
__device__ int   g_total;
__device__ float g_agg    [(size_t)MAXN * 4 * HDIM];          // [n][c][h], 102.4 MB
// bf16 split weights, [c][o][k256]: k<128 -> Wroot[o][k], else Wrel[o][k-128]
__device__ __nv_bfloat16 g_whi[4 * 128 * 256];
__device__ __nv_bfloat16 g_wlo[4 * 128 * 256];

// ---------------- helpers ------------------------------------------------------
__device__ __forceinline__ uint32_t smem_u32(const void* p) {
    uint32_t a;
    asm("{ .reg .u64 t; cvta.to.shared.u64 t, %1; cvt.u32.u64 %0, t; }"
        : "=r"(a) : "l"(p));
    return a;
}

__device__ __forceinline__ void ldsm_x4(uint32_t* r, uint32_t addr) {
    asm volatile("ldmatrix.sync.aligned.m8n8.x4.shared.b16 {%0,%1,%2,%3}, [%4];"
                 : "=r"(r[0]), "=r"(r[1]), "=r"(r[2]), "=r"(r[3]) : "r"(addr));
}
__device__ __forceinline__ void mma_bf16(float* d, const uint32_t* a,
                                         uint32_t b0, uint32_t b1) {
    asm volatile(
        "mma.sync.aligned.m16n8k16.row.col.f32.bf16.bf16.f32 "
        "{%0,%1,%2,%3}, {%4,%5,%6,%7}, {%8,%9}, {%0,%1,%2,%3};"
        : "+f"(d[0]), "+f"(d[1]), "+f"(d[2]), "+f"(d[3])
        : "r"(a[0]), "r"(a[1]), "r"(a[2]), "r"(a[3]), "r"(b0), "r"(b1));
}

// ---------------- CSR / agg kernels -------------------------------------------
__global__ void detect_kernel(const void* __restrict__ ei, int e, int n) {
    const long long* p64 = (const long long*)ei;
    int cnt = e < 256 ? e : 256;
    int ok = 1;
    for (int i = 0; i < cnt; i++) {
        long long v = p64[i];
        if (v < 0 || v >= (long long)n) { ok = 0; break; }
    }
    g_is64 = ok;
}

__global__ void zero_counts_kernel(int n) {
    int i = blockIdx.x * blockDim.x + threadIdx.x;
    if (i < n) g_counts[i] = 0;
}

__global__ void count_kernel(const void* __restrict__ ei, int e) {
    int i = blockIdx.x * blockDim.x + threadIdx.x;
    if (i < e) {
        int r;
        if (g_is64) r = (int)((const long long*)ei)[i];
        else        r = ((const int*)ei)[i];
        atomicAdd(&g_counts[r], 1);
    }
}

__global__ void scan1_kernel(int n) {
    int tid  = threadIdx.x;
    int gid  = blockIdx.x * 256 + tid;
    int lane = tid & 31;
    int wid  = tid >> 5;
    int v = (gid < n) ? g_counts[gid] : 0;
    int s = v;
#pragma unroll
    for (int o = 1; o < 32; o <<= 1) {
        int t = __shfl_up_sync(0xFFFFFFFFu, s, o);
        if (lane >= o) s += t;
    }
    __shared__ int wtot[8];
    __shared__ int woff[8];
    if (lane == 31) wtot[wid] = s;
    __syncthreads();
    if (tid == 0) {
        int r = 0;
#pragma unroll
        for (int w = 0; w < 8; w++) { woff[w] = r; r += wtot[w]; }
        g_bsum[blockIdx.x] = r;
    }
    __syncthreads();
    int excl = s - v + woff[wid];
    if (gid < n) g_offsets[gid] = excl;
}

__global__ void scan2_kernel(int nb) {
    int tid  = threadIdx.x;
    int lane = tid & 31;
    int wid  = tid >> 5;
    int v = (tid < nb) ? g_bsum[tid] : 0;
    int s = v;
#pragma unroll
    for (int o = 1; o < 32; o <<= 1) {
        int t = __shfl_up_sync(0xFFFFFFFFu, s, o);
        if (lane >= o) s += t;
    }
    __shared__ int wtot[8];
    __shared__ int woff[8];
    if (lane == 31) wtot[wid] = s;
    __syncthreads();
    if (tid == 0) {
        int r = 0;
#pragma unroll
        for (int w = 0; w < 8; w++) { woff[w] = r; r += wtot[w]; }
        g_total = r;
    }
    __syncthreads();
    g_boff[tid] = s - v + woff[wid];
}

__global__ void scan3_kernel(int n) {
    int gid = blockIdx.x * 256 + threadIdx.x;
    if (gid < n) {
        int off = g_offsets[gid] + g_boff[gid >> 8];
        g_offsets[gid] = off;
        g_cursor[gid]  = off;
    }
    if (gid == 0) g_offsets[n] = g_total;
}

__global__ void fill_kernel(const void* __restrict__ ei, int e) {
    int i = blockIdx.x * blockDim.x + threadIdx.x;
    if (i < e) {
        int r, c;
        if (g_is64) {
            const long long* p = (const long long*)ei;
            r = (int)p[i];
            c = (int)p[(size_t)e + i];
        } else {
            const int* p = (const int*)ei;
            r = p[i];
            c = p[(size_t)e + i];
        }
        int pos = atomicAdd(&g_cursor[r], 1);
        g_sorted[pos] = c;
    }
}

// one block (128 threads) per node; unroll-4 gather; streaming store so the
// g_agg write-allocate doesn't evict x (102MB, L2-resident) from L2.
__global__ void agg_kernel(const float* __restrict__ x) {
    int nidx = blockIdx.x;
    int tid  = threadIdx.x;
    int beg = g_offsets[nidx];
    int end = g_offsets[nidx + 1];
    const float4* xv = (const float4*)x;
    float4 acc = make_float4(0.f, 0.f, 0.f, 0.f);
    int j = beg;
    for (; j + 3 < end; j += 4) {
        int c0 = g_sorted[j];
        int c1 = g_sorted[j + 1];
        int c2 = g_sorted[j + 2];
        int c3 = g_sorted[j + 3];
        float4 v0 = xv[(size_t)c0 * 128 + tid];
        float4 v1 = xv[(size_t)c1 * 128 + tid];
        float4 v2 = xv[(size_t)c2 * 128 + tid];
        float4 v3 = xv[(size_t)c3 * 128 + tid];
        acc.x += v0.x; acc.y += v0.y; acc.z += v0.z; acc.w += v0.w;
        acc.x += v1.x; acc.y += v1.y; acc.z += v1.z; acc.w += v1.w;
        acc.x += v2.x; acc.y += v2.y; acc.z += v2.z; acc.w += v2.w;
        acc.x += v3.x; acc.y += v3.y; acc.z += v3.z; acc.w += v3.w;
    }
    for (; j < end; j++) {
        int c0 = g_sorted[j];
        float4 v0 = xv[(size_t)c0 * 128 + tid];
        acc.x += v0.x; acc.y += v0.y; acc.z += v0.z; acc.w += v0.w;
    }
    __stcs(((float4*)g_agg) + (size_t)nidx * 128 + tid, acc);
}

// weight prep: bf16 hi/lo split, [c][o][k256]
__global__ void wprep_kernel(const float* __restrict__ Wsrel,
                             const float* __restrict__ Wsroot,
                             const float* __restrict__ Wvrel,
                             const float* __restrict__ Wvroot) {
    int idx = blockIdx.x * blockDim.x + threadIdx.x;
    const int total = 4 * 128 * 256;
    if (idx >= total) return;
    int k = idx & 255;
    int o = (idx >> 8) & 127;
    int c = idx >> 15;
    const float* root = (c == 0) ? Wsroot : Wvroot;
    const float* rel  = (c == 0) ? Wsrel  : Wvrel;
    float w = (k < 128) ? root[o * 128 + k] : rel[o * 128 + (k - 128)];
    __nv_bfloat16 hi = __float2bfloat16(w);
    __nv_bfloat16 lo = __float2bfloat16(w - __bfloat162float(hi));
    g_whi[idx] = hi;
    g_wlo[idx] = lo;
}

// ---------------- HMMA GEMM ----------------------------------------------------
// grid (ceil(n/128), 4), 256 threads (8 warps 4x2), dyn smem 64KB.
// out[n,c,:] = [x | agg](n,c,:) @ Wcat_c^T (+bias if c==0), bf16 split 3-product.
// Inner loop hoists ALL fragments once per k-step (a_hi, a_lo, b_hi, b_lo:
// 12 ldsm.x4) and issues the 3 products (hi*hi, lo*hi, hi*lo: 48 mma) —
// sharing b_hi between two products cuts LDSM traffic 18->12 per k-step.

#define SM_AHI 0
#define SM_ALO 16384
#define SM_BHI 32768
#define SM_BLO 49152
#define SM_TOT 65536

__global__ __launch_bounds__(256) void hmma_gemm_kernel(const float* __restrict__ x,
                                                        const float* __restrict__ bias,
                                                        float* __restrict__ out,
                                                        int n) {
    extern __shared__ char smem[];
    uint32_t sb = smem_u32(smem);

    int tid  = threadIdx.x;
    int lane = tid & 31;
    int warp = tid >> 5;
    int wm   = warp & 3;     // 0..3  -> 32 M rows each
    int wn   = warp >> 2;    // 0..1  -> 64 N cols each
    int c    = blockIdx.y;
    int row0 = blockIdx.x * 128;

    int q   = lane >> 3;     // ldmatrix lane group
    int rib = lane & 7;
    int qm  = (q & 1) * 8;
    int qk  = q >> 1;

    // fixed ldmatrix row indices
    int rA0 = wm * 32 + qm + rib;
    int rA1 = rA0 + 16;
    int rB[4];
#pragma unroll
    for (int p = 0; p < 4; p++) rB[p] = wn * 64 + p * 16 + qm + rib;

    float acc[2][8][4];
#pragma unroll
    for (int mt = 0; mt < 2; mt++)
#pragma unroll
        for (int nt = 0; nt < 8; nt++)
#pragma unroll
            for (int i = 0; i < 4; i++) acc[mt][nt][i] = 0.f;

    for (int k0c = 0; k0c < 4; k0c++) {
        if (k0c) __syncthreads();   // protect smem reuse

        // ---- A chunk: 128 rows x 64 k fp32 -> bf16 hi/lo swizzled ----
        const float* asrc = (k0c < 2) ? x : (const float*)g_agg;
        int kbase = (k0c & 1) * 64;
#pragma unroll
        for (int it = 0; it < 8; it++) {
            int idx = it * 256 + tid;
            int r   = idx >> 4;           // 0..127
            int f4  = idx & 15;           // float4 within row
            float4 v = make_float4(0.f, 0.f, 0.f, 0.f);
            int nn = row0 + r;
            if (nn < n)
                v = *(const float4*)&asrc[((size_t)nn * 4 + c) * 128 + kbase + f4 * 4];
            __nv_bfloat16 h0 = __float2bfloat16(v.x);
            __nv_bfloat16 h1 = __float2bfloat16(v.y);
            __nv_bfloat16 h2 = __float2bfloat16(v.z);
            __nv_bfloat16 h3 = __float2bfloat16(v.w);
            __nv_bfloat16 l0 = __float2bfloat16(v.x - __bfloat162float(h0));
            __nv_bfloat16 l1 = __float2bfloat16(v.y - __bfloat162float(h1));
            __nv_bfloat16 l2 = __float2bfloat16(v.z - __bfloat162float(h2));
            __nv_bfloat16 l3 = __float2bfloat16(v.w - __bfloat162float(h3));
            uint2 hv, lv;
            hv.x = (uint32_t)__bfloat16_as_ushort(h0) | ((uint32_t)__bfloat16_as_ushort(h1) << 16);
            hv.y = (uint32_t)__bfloat16_as_ushort(h2) | ((uint32_t)__bfloat16_as_ushort(h3) << 16);
            lv.x = (uint32_t)__bfloat16_as_ushort(l0) | ((uint32_t)__bfloat16_as_ushort(l1) << 16);
            lv.y = (uint32_t)__bfloat16_as_ushort(l2) | ((uint32_t)__bfloat16_as_ushort(l3) << 16);
            int kc   = f4 >> 1;
            int sub8 = (f4 & 1) << 3;
            uint32_t off = (uint32_t)(r * 128 + ((kc ^ (r & 7)) << 4) + sub8);
            *(uint2*)(smem + SM_AHI + off) = hv;
            *(uint2*)(smem + SM_ALO + off) = lv;
        }

        // ---- B chunk: 128 n x 64 k bf16 hi/lo swizzled ----
        const __nv_bfloat16* wh = g_whi + (size_t)c * 128 * 256 + k0c * 64;
        const __nv_bfloat16* wl = g_wlo + (size_t)c * 128 * 256 + k0c * 64;
#pragma unroll
        for (int it = 0; it < 4; it++) {
            int id = it * 256 + tid;
            int nr = id >> 3;             // 0..127
            int kc = id & 7;              // 16B chunk
            uint4 hv = *(const uint4*)&wh[(size_t)nr * 256 + kc * 8];
            uint4 lv = *(const uint4*)&wl[(size_t)nr * 256 + kc * 8];
            uint32_t off = (uint32_t)(nr * 128 + ((kc ^ (nr & 7)) << 4));
            *(uint4*)(smem + SM_BHI + off) = hv;
            *(uint4*)(smem + SM_BLO + off) = lv;
        }

        __syncthreads();

        // ---- compute: per k-step load all fragments once, 3 products ----
#pragma unroll
        for (int ks = 0; ks < 4; ks++) {
            int kc = ks * 2 + qk;
            uint32_t ah0[4], ah1[4], al0[4], al1[4];
            uint32_t offA0 = (uint32_t)(rA0 * 128 + ((kc ^ (rA0 & 7)) << 4));
            uint32_t offA1 = (uint32_t)(rA1 * 128 + ((kc ^ (rA1 & 7)) << 4));
            ldsm_x4(ah0, sb + SM_AHI + offA0);
            ldsm_x4(ah1, sb + SM_AHI + offA1);
            ldsm_x4(al0, sb + SM_ALO + offA0);
            ldsm_x4(al1, sb + SM_ALO + offA1);
            uint32_t bh[4][4], bl[4][4];
#pragma unroll
            for (int pr = 0; pr < 4; pr++) {
                uint32_t offB = (uint32_t)(rB[pr] * 128 + ((kc ^ (rB[pr] & 7)) << 4));
                ldsm_x4(bh[pr], sb + SM_BHI + offB);
                ldsm_x4(bl[pr], sb + SM_BLO + offB);
            }
#pragma unroll
            for (int pr = 0; pr < 4; pr++) {
                // hi * hi
                mma_bf16(acc[0][pr * 2],     ah0, bh[pr][0], bh[pr][2]);
                mma_bf16(acc[0][pr * 2 + 1], ah0, bh[pr][1], bh[pr][3]);
                mma_bf16(acc[1][pr * 2],     ah1, bh[pr][0], bh[pr][2]);
                mma_bf16(acc[1][pr * 2 + 1], ah1, bh[pr][1], bh[pr][3]);
                // lo * hi
                mma_bf16(acc[0][pr * 2],     al0, bh[pr][0], bh[pr][2]);
                mma_bf16(acc[0][pr * 2 + 1], al0, bh[pr][1], bh[pr][3]);
                mma_bf16(acc[1][pr * 2],     al1, bh[pr][0], bh[pr][2]);
                mma_bf16(acc[1][pr * 2 + 1], al1, bh[pr][1], bh[pr][3]);
                // hi * lo
                mma_bf16(acc[0][pr * 2],     ah0, bl[pr][0], bl[pr][2]);
                mma_bf16(acc[0][pr * 2 + 1], ah0, bl[pr][1], bl[pr][3]);
                mma_bf16(acc[1][pr * 2],     ah1, bl[pr][0], bl[pr][2]);
                mma_bf16(acc[1][pr * 2 + 1], ah1, bl[pr][1], bl[pr][3]);
            }
        }
    }

    // ---- epilogue ----
    float2 bv[8];
#pragma unroll
    for (int nt = 0; nt < 8; nt++) bv[nt] = make_float2(0.f, 0.f);
    if (c == 0) {
#pragma unroll
        for (int nt = 0; nt < 8; nt++) {
            int nn = wn * 64 + nt * 8 + (lane & 3) * 2;
            bv[nt] = *(const float2*)&bias[nn];
        }
    }
#pragma unroll
    for (int mt = 0; mt < 2; mt++) {
        int r0 = row0 + wm * 32 + mt * 16 + (lane >> 2);
        int r1 = r0 + 8;
#pragma unroll
        for (int nt = 0; nt < 8; nt++) {
            int nn = wn * 64 + nt * 8 + (lane & 3) * 2;
            if (r0 < n) {
                float2 v = make_float2(acc[mt][nt][0] + bv[nt].x,
                                       acc[mt][nt][1] + bv[nt].y);
                *(float2*)&out[((size_t)r0 * 4 + c) * 128 + nn] = v;
            }
            if (r1 < n) {
                float2 v = make_float2(acc[mt][nt][2] + bv[nt].x,
                                       acc[mt][nt][3] + bv[nt].y);
                *(float2*)&out[((size_t)r1 * 4 + c) * 128 + nn] = v;
            }
        }
    }
}

// ---------------- launch -----------------------------------------------------

extern "C" void kernel_launch(void* const* d_in, const int* in_sizes, int n_in,
                              void* d_out, int out_size) {
    const float* x      = (const float*)d_in[0];
    const void*  ei     = d_in[1];
    const float* Wsrel  = (const float*)d_in[2];
    const float* Wsroot = (const float*)d_in[3];
    const float* bs     = (const float*)d_in[4];
    const float* Wvrel  = (const float*)d_in[5];
    const float* Wvroot = (const float*)d_in[6];
    float*       out    = (float*)d_out;

    int n = in_sizes[0] / (4 * HDIM);   // 50000
    int e = in_sizes[1] / 2;            // 500000
    int nb = (n + 255) / 256;

    cudaFuncSetAttribute(hmma_gemm_kernel,
                         cudaFuncAttributeMaxDynamicSharedMemorySize, SM_TOT);

    detect_kernel<<<1, 1>>>(ei, e, n);

    zero_counts_kernel<<<(n + 255) / 256, 256>>>(n);
    count_kernel<<<(e + 255) / 256, 256>>>(ei, e);
    scan1_kernel<<<nb, 256>>>(n);
    scan2_kernel<<<1, 256>>>(nb);
    scan3_kernel<<<nb, 256>>>(n);
    fill_kernel<<<(e + 255) / 256, 256>>>(ei, e);

    wprep_kernel<<<(4 * 128 * 256 + 255) / 256, 256>>>(Wsrel, Wsroot, Wvrel, Wvroot);

    agg_kernel<<<n, 128>>>(x);

    dim3 grid((n + 127) / 128, 4);
    hmma_gemm_kernel<<<grid, 256, SM_TOT>>>(x, bs, out, n);
}